// round 3
// baseline (speedup 1.0000x reference)
#include <cuda_runtime.h>

#define SEQ     1024
#define HDIM    640
#define G4      2560
#define NNODES  1024
#define NEDGES  16384
#define BSZ     16

// ---------------- scratch (device globals; no runtime allocation) ----------------
__device__ float g_xW[SEQ * G4];          // 10.5 MB  LSTM input projections
__device__ float g_bufA[SEQ * HDIM];      // 2.6 MB   ping
__device__ float g_bufB[SEQ * HDIM];      // 2.6 MB   pong
__device__ float g_gh[NNODES * 320];      // GCN gemm out
__device__ float g_gy[NNODES * 320];      // GCN scatter out
__device__ float g_Wt[640 * 320];         // transposed GCN weight
__device__ int   g_deg[NNODES];
__device__ float g_dinv[NNODES];
__device__ float g_selfnorm[NNODES];
__device__ float g_enorm[NEDGES];
__device__ unsigned g_bar_cnt;
__device__ unsigned g_bar_gen;

// ---------------- grid-wide sense barrier (all CTAs co-resident) ----------------
__device__ __forceinline__ void grid_barrier_dev() {
    __syncthreads();
    if (threadIdx.x == 0) {
        __threadfence();
        volatile unsigned* genp = &g_bar_gen;
        unsigned my = *genp;
        if (atomicAdd(&g_bar_cnt, 1u) == gridDim.x - 1u) {
            g_bar_cnt = 0u;
            __threadfence();
            *genp = my + 1u;
        } else {
            while (*genp == my) { }
            __threadfence();
        }
    }
    __syncthreads();
}

// ---------------- fp32 NT GEMM: C[M,N] = A[M,K] * B[N,K]^T (+bias1+bias2) ----------------
// BM=128 BN=64 BK=16, 256 threads, 8x4 per thread
__global__ __launch_bounds__(256) void sgemm_nt(
    const float* __restrict__ A, const float* __restrict__ B,
    const float* __restrict__ bias1, const float* __restrict__ bias2,
    float* __restrict__ C, int M, int N, int K)
{
    __shared__ float As[16][128];
    __shared__ float Bs[16][64];
    const int tx = threadIdx.x, ty = threadIdx.y;
    const int tid = ty * 16 + tx;
    const int m0 = blockIdx.y * 128, n0 = blockIdx.x * 64;

    float acc[8][4];
#pragma unroll
    for (int i = 0; i < 8; i++)
#pragma unroll
        for (int j = 0; j < 4; j++) acc[i][j] = 0.f;

    const bool k4ok = ((K & 3) == 0);
    const int ntiles = (K + 15) >> 4;

    for (int kt = 0; kt < ntiles; kt++) {
        const int kb = kt * 16;
        // A tile: 2 float4 per thread
#pragma unroll
        for (int i = 0; i < 2; i++) {
            int fid = tid * 2 + i;
            int r = fid >> 2;
            int kk = (fid & 3) << 2;
            float4 v = make_float4(0.f, 0.f, 0.f, 0.f);
            if (m0 + r < M) {
                const float* ap = A + (size_t)(m0 + r) * K + kb + kk;
                if (k4ok && kb + kk + 3 < K) v = *(const float4*)ap;
                else {
                    if (kb + kk + 0 < K) v.x = ap[0];
                    if (kb + kk + 1 < K) v.y = ap[1];
                    if (kb + kk + 2 < K) v.z = ap[2];
                    if (kb + kk + 3 < K) v.w = ap[3];
                }
            }
            As[kk + 0][r] = v.x; As[kk + 1][r] = v.y;
            As[kk + 2][r] = v.z; As[kk + 3][r] = v.w;
        }
        // B tile: 1 float4 per thread
        {
            int r = tid >> 2;
            int kk = (tid & 3) << 2;
            float4 v = make_float4(0.f, 0.f, 0.f, 0.f);
            if (n0 + r < N) {
                const float* bp = B + (size_t)(n0 + r) * K + kb + kk;
                if (k4ok && kb + kk + 3 < K) v = *(const float4*)bp;
                else {
                    if (kb + kk + 0 < K) v.x = bp[0];
                    if (kb + kk + 1 < K) v.y = bp[1];
                    if (kb + kk + 2 < K) v.z = bp[2];
                    if (kb + kk + 3 < K) v.w = bp[3];
                }
            }
            Bs[kk + 0][r] = v.x; Bs[kk + 1][r] = v.y;
            Bs[kk + 2][r] = v.z; Bs[kk + 3][r] = v.w;
        }
        __syncthreads();
#pragma unroll
        for (int k = 0; k < 16; k++) {
            float4 b4 = *(const float4*)&Bs[k][tx * 4];
            float4 a0 = *(const float4*)&As[k][ty * 8];
            float4 a1 = *(const float4*)&As[k][ty * 8 + 4];
            float a[8] = {a0.x, a0.y, a0.z, a0.w, a1.x, a1.y, a1.z, a1.w};
            float bb[4] = {b4.x, b4.y, b4.z, b4.w};
#pragma unroll
            for (int i = 0; i < 8; i++)
#pragma unroll
                for (int j = 0; j < 4; j++)
                    acc[i][j] += a[i] * bb[j];
        }
        __syncthreads();
    }
#pragma unroll
    for (int i = 0; i < 8; i++) {
        int m = m0 + ty * 8 + i;
        if (m >= M) continue;
#pragma unroll
        for (int j = 0; j < 4; j++) {
            int n = n0 + tx * 4 + j;
            if (n < N) {
                float v = acc[i][j];
                if (bias1) v += bias1[n];
                if (bias2) v += bias2[n];
                C[(size_t)m * N + n] = v;
            }
        }
    }
}

// ---------------- persistent LSTM recurrence ----------------
// 128 CTAs x 640 threads. CTA k owns hidden units [5k, 5k+5).
// warp w: unit u=w>>2, gate g=w&3, row = g*640 + (5k+u). Whh row in registers.
__global__ __launch_bounds__(640, 1) void lstm_rec(
    const float* __restrict__ xW,   // [1024, 2560] (biases folded in)
    const float* __restrict__ Whh,  // [2560, 640]
    float* __restrict__ seq_out)    // [1024, 640]
{
    __shared__ float h_s[640];
    __shared__ float dots[5][4];
    __shared__ float c_s[5];

    const int tid = threadIdx.x;
    const int w = tid >> 5, l = tid & 31;
    const int k = blockIdx.x;
    const int u = w >> 2;
    const int gsel = w & 3;
    const int uglob = 5 * k + u;
    const int row = gsel * 640 + uglob;

    float wreg[20];
    const float* wp = Whh + (size_t)row * 640 + 20 * l;
#pragma unroll
    for (int i = 0; i < 20; i++) wreg[i] = wp[i];
    if (tid < 5) c_s[tid] = 0.f;
    __syncthreads();

    for (int t = 0; t < SEQ; t++) {
        float acc = 0.f;
        if (t > 0) {
            h_s[tid] = __ldcg(seq_out + (size_t)(t - 1) * 640 + tid);
            __syncthreads();
            const float4* hp = (const float4*)(h_s + 20 * l);
#pragma unroll
            for (int i = 0; i < 5; i++) {
                float4 v = hp[i];
                acc += wreg[4 * i + 0] * v.x + wreg[4 * i + 1] * v.y
                     + wreg[4 * i + 2] * v.z + wreg[4 * i + 3] * v.w;
            }
        }
#pragma unroll
        for (int off = 16; off > 0; off >>= 1)
            acc += __shfl_down_sync(0xffffffffu, acc, off);
        if (l == 0) dots[u][gsel] = acc;
        __syncthreads();

        if (tid < 5) {
            const int uu = tid;
            const int ug = 5 * k + uu;
            const float* xwt = xW + (size_t)t * G4;
            float gi = xwt[ug]        + dots[uu][0];
            float gf = xwt[640 + ug]  + dots[uu][1];
            float gg = xwt[1280 + ug] + dots[uu][2];
            float go = xwt[1920 + ug] + dots[uu][3];
            float iv = 1.f / (1.f + __expf(-gi));
            float fv = 1.f / (1.f + __expf(-gf));
            float gv = tanhf(gg);
            float ov = 1.f / (1.f + __expf(-go));
            float c = fv * c_s[uu] + iv * gv;
            c_s[uu] = c;
            seq_out[(size_t)t * 640 + ug] = ov * tanhf(c);
        }
        grid_barrier_dev();
    }
}

// ---------------- graph prep ----------------
__global__ void zero_deg(int* deg) {
    int i = blockIdx.x * blockDim.x + threadIdx.x;
    if (i < NNODES) deg[i] = 0;
}
__global__ void count_deg(const int* __restrict__ dst, int* deg) {
    int e = blockIdx.x * blockDim.x + threadIdx.x;
    if (e < NEDGES) atomicAdd(&deg[dst[e]], 1);
}
__global__ void finalize_deg(const int* __restrict__ deg, float* dinv, float* selfnorm) {
    int i = blockIdx.x * blockDim.x + threadIdx.x;
    if (i < NNODES) {
        float d = rsqrtf((float)(deg[i] + 1));   // +1 self loop
        dinv[i] = d;
        selfnorm[i] = d * d;
    }
}
__global__ void edge_norm(const int* __restrict__ src, const int* __restrict__ dst,
                          const float* __restrict__ dinv, float* enorm) {
    int e = blockIdx.x * blockDim.x + threadIdx.x;
    if (e < NEDGES) enorm[e] = dinv[src[e]] * dinv[dst[e]];
}
__global__ void transpose_k(const float* __restrict__ W, float* __restrict__ Wt,
                            int Cin, int Cout) {
    int idx = blockIdx.x * blockDim.x + threadIdx.x;
    if (idx < Cin * Cout) {
        int i = idx / Cout, o = idx % Cout;
        Wt[o * Cin + i] = W[idx];
    }
}

// ---------------- GCN scatter ----------------
__global__ void scatter_init(const float* __restrict__ h, const float* __restrict__ selfnorm,
                             float* __restrict__ y, int C) {
    int idx = blockIdx.x * blockDim.x + threadIdx.x;
    if (idx < NNODES * C) {
        int i = idx / C;
        y[idx] = selfnorm[i] * h[idx];
    }
}
__global__ void scatter_edges(const float* __restrict__ h, const float* __restrict__ enorm,
                              const int* __restrict__ src, const int* __restrict__ dst,
                              float* __restrict__ y, int C) {
    int idx = blockIdx.x * blockDim.x + threadIdx.x;
    if (idx < NEDGES * C) {
        int e = idx / C, c = idx - e * C;
        atomicAdd(&y[dst[e] * C + c], enorm[e] * h[src[e] * C + c]);
    }
}

// ---------------- bias + leaky + batchnorm (per-column CTA) ----------------
__global__ void bias_leaky_bn(const float* __restrict__ y, const float* __restrict__ b,
                              float* __restrict__ out, int C) {
    const int c = blockIdx.x;
    const int tid = threadIdx.x;
    const float bias = b[c];
    float s = 0.f, sq = 0.f;
    for (int r = tid; r < NNODES; r += 256) {
        float v = y[r * C + c] + bias;
        v = (v > 0.f) ? v : 0.01f * v;
        s += v; sq += v * v;
    }
    __shared__ float rs[256], rq[256];
    rs[tid] = s; rq[tid] = sq;
    __syncthreads();
    for (int o = 128; o > 0; o >>= 1) {
        if (tid < o) { rs[tid] += rs[tid + o]; rq[tid] += rq[tid + o]; }
        __syncthreads();
    }
    float mean = rs[0] * (1.f / NNODES);
    float var = rq[0] * (1.f / NNODES) - mean * mean;
    float rstd = rsqrtf(var + 1e-5f);
    for (int r = tid; r < NNODES; r += 256) {
        float v = y[r * C + c] + bias;
        v = (v > 0.f) ? v : 0.01f * v;
        out[r * C + c] = (v - mean) * rstd;
    }
}

// ---------------- head: segment sum + concat + 3 FC ----------------
__global__ void head_kernel(const float* __restrict__ x,   // [1024, 50]
                            const float* __restrict__ gender, const float* __restrict__ handed,
                            const float* __restrict__ W1, const float* __restrict__ b1,
                            const float* __restrict__ W2, const float* __restrict__ b2,
                            const float* __restrict__ W3, const float* __restrict__ b3,
                            float* __restrict__ out) {
    const int b = blockIdx.x;
    const int tid = threadIdx.x;
    __shared__ float feat[52];
    __shared__ float y1[32], y2[16];
    if (tid < 50) {
        float s = 0.f;
        for (int r = 0; r < 64; r++) s += x[(b * 64 + r) * 50 + tid];
        feat[tid] = s;
    }
    if (tid == 50) feat[50] = gender[b];
    if (tid == 51) feat[51] = handed[b];
    __syncthreads();
    if (tid < 32) {
        float s = b1[tid];
        for (int i = 0; i < 52; i++) s += feat[i] * W1[tid * 52 + i];
        y1[tid] = s;
    }
    __syncthreads();
    if (tid < 16) {
        float s = b2[tid];
        for (int i = 0; i < 32; i++) s += y1[i] * W2[tid * 32 + i];
        y2[tid] = s;
    }
    __syncthreads();
    if (tid == 0) {
        float s = b3[0];
        for (int i = 0; i < 16; i++) s += y2[i] * W3[i];
        out[b] = s;
    }
}

// ---------------- host ----------------
extern "C" void kernel_launch(void* const* d_in, const int* in_sizes, int n_in,
                              void* d_out, int out_size) {
    const float* x_in   = (const float*)d_in[0];
    const int*   eidx   = (const int*)d_in[1];
    const float* gender = (const float*)d_in[2];
    const float* handed = (const float*)d_in[3];
    const float* Wih[3] = {(const float*)d_in[4], (const float*)d_in[8],  (const float*)d_in[12]};
    const float* Whh[3] = {(const float*)d_in[5], (const float*)d_in[9],  (const float*)d_in[13]};
    const float* bih[3] = {(const float*)d_in[6], (const float*)d_in[10], (const float*)d_in[14]};
    const float* bhh[3] = {(const float*)d_in[7], (const float*)d_in[11], (const float*)d_in[15]};
    const float* gcnW[4] = {(const float*)d_in[16], (const float*)d_in[18], (const float*)d_in[20], (const float*)d_in[22]};
    const float* gcnB[4] = {(const float*)d_in[17], (const float*)d_in[19], (const float*)d_in[21], (const float*)d_in[23]};
    const float* fcW[3] = {(const float*)d_in[24], (const float*)d_in[26], (const float*)d_in[28]};
    const float* fcB[3] = {(const float*)d_in[25], (const float*)d_in[27], (const float*)d_in[29]};

    float *xW, *bufA, *bufB, *gh, *gy, *Wt, *dinv, *selfnorm, *enorm;
    int* deg;
    cudaGetSymbolAddress((void**)&xW, g_xW);
    cudaGetSymbolAddress((void**)&bufA, g_bufA);
    cudaGetSymbolAddress((void**)&bufB, g_bufB);
    cudaGetSymbolAddress((void**)&gh, g_gh);
    cudaGetSymbolAddress((void**)&gy, g_gy);
    cudaGetSymbolAddress((void**)&Wt, g_Wt);
    cudaGetSymbolAddress((void**)&deg, g_deg);
    cudaGetSymbolAddress((void**)&dinv, g_dinv);
    cudaGetSymbolAddress((void**)&selfnorm, g_selfnorm);
    cudaGetSymbolAddress((void**)&enorm, g_enorm);

    const int* src = eidx;
    const int* dst = eidx + NEDGES;
    dim3 tb(16, 16);

    // ---- LSTM ----
    sgemm_nt<<<dim3(G4 / 64, SEQ / 128), tb>>>(x_in, Wih[0], bih[0], bhh[0], xW, SEQ, G4, 8500);
    lstm_rec<<<128, 640>>>(xW, Whh[0], bufA);
    sgemm_nt<<<dim3(G4 / 64, SEQ / 128), tb>>>(bufA, Wih[1], bih[1], bhh[1], xW, SEQ, G4, HDIM);
    lstm_rec<<<128, 640>>>(xW, Whh[1], bufB);
    sgemm_nt<<<dim3(G4 / 64, SEQ / 128), tb>>>(bufB, Wih[2], bih[2], bhh[2], xW, SEQ, G4, HDIM);
    lstm_rec<<<128, 640>>>(xW, Whh[2], bufA);

    // ---- graph prep ----
    zero_deg<<<4, 256>>>(deg);
    count_deg<<<NEDGES / 256, 256>>>(dst, deg);
    finalize_deg<<<4, 256>>>(deg, dinv, selfnorm);
    edge_norm<<<NEDGES / 256, 256>>>(src, dst, dinv, enorm);

    // ---- GCN layers ----
    const int cins[4]  = {640, 320, 180, 90};
    const int couts[4] = {320, 180, 90, 50};
    float* xcur = bufA;
    float* xnext = bufB;
    for (int l = 0; l < 4; l++) {
        int Cin = cins[l], Cout = couts[l];
        transpose_k<<<(Cin * Cout + 255) / 256, 256>>>(gcnW[l], Wt, Cin, Cout);
        sgemm_nt<<<dim3((Cout + 63) / 64, NNODES / 128), tb>>>(xcur, Wt, nullptr, nullptr,
                                                               gh, NNODES, Cout, Cin);
        scatter_init<<<(NNODES * Cout + 255) / 256, 256>>>(gh, selfnorm, gy, Cout);
        scatter_edges<<<(NEDGES * Cout + 255) / 256, 256>>>(gh, enorm, src, dst, gy, Cout);
        bias_leaky_bn<<<Cout, 256>>>(gy, gcnB[l], xnext, Cout);
        float* tmp = xcur; xcur = xnext; xnext = tmp;
    }

    // ---- head ----
    head_kernel<<<BSZ, 64>>>(xcur, gender, handed,
                             fcW[0], fcB[0], fcW[1], fcB[1], fcW[2], fcB[2],
                             (float*)d_out);
}

// round 4
// speedup vs baseline: 1.0032x; 1.0032x over previous
#include <cuda_runtime.h>

#define SEQ     1024
#define HDIM    640
#define G4      2560
#define NNODES  1024
#define NEDGES  16384
#define BSZ     16

// ---------------- scratch (device globals; no runtime allocation) ----------------
__device__ float g_xW[SEQ * G4];          // 10.5 MB  LSTM input projections
__device__ float g_bufA[SEQ * HDIM];      // 2.6 MB   ping
__device__ float g_bufB[SEQ * HDIM];      // 2.6 MB   pong
__device__ float g_gh[NNODES * 320];      // GCN gemm out
__device__ float g_gy[NNODES * 320];      // GCN scatter out
__device__ float g_Wt[640 * 320];         // transposed GCN weight
__device__ int   g_deg[NNODES];
__device__ float g_dinv[NNODES];
__device__ float g_selfnorm[NNODES];
__device__ float g_enorm[NEDGES];
__device__ unsigned g_bar_cnt;
__device__ unsigned g_bar_gen;

// ---------------- grid-wide sense barrier (all CTAs co-resident) ----------------
__device__ __forceinline__ void grid_barrier_dev() {
    __syncthreads();
    if (threadIdx.x == 0) {
        __threadfence();
        volatile unsigned* genp = &g_bar_gen;
        unsigned my = *genp;
        if (atomicAdd(&g_bar_cnt, 1u) == gridDim.x - 1u) {
            g_bar_cnt = 0u;
            __threadfence();
            *genp = my + 1u;
        } else {
            while (*genp == my) { }
            __threadfence();
        }
    }
    __syncthreads();
}

// ---------------- fp32 NT GEMM: C[M,N] = A[M,K] * B[N,K]^T (+bias1+bias2) ----------------
// BM=128 BN=64 BK=16, 256 threads, 8x4 per thread
__global__ __launch_bounds__(256) void sgemm_nt(
    const float* __restrict__ A, const float* __restrict__ B,
    const float* __restrict__ bias1, const float* __restrict__ bias2,
    float* __restrict__ C, int M, int N, int K)
{
    __shared__ float As[16][128];
    __shared__ float Bs[16][64];
    const int tx = threadIdx.x, ty = threadIdx.y;
    const int tid = ty * 16 + tx;
    const int m0 = blockIdx.y * 128, n0 = blockIdx.x * 64;

    float acc[8][4];
#pragma unroll
    for (int i = 0; i < 8; i++)
#pragma unroll
        for (int j = 0; j < 4; j++) acc[i][j] = 0.f;

    const bool k4ok = ((K & 3) == 0);
    const int ntiles = (K + 15) >> 4;

    for (int kt = 0; kt < ntiles; kt++) {
        const int kb = kt * 16;
        // A tile: 2 float4 per thread
#pragma unroll
        for (int i = 0; i < 2; i++) {
            int fid = tid * 2 + i;
            int r = fid >> 2;
            int kk = (fid & 3) << 2;
            float4 v = make_float4(0.f, 0.f, 0.f, 0.f);
            if (m0 + r < M) {
                const float* ap = A + (size_t)(m0 + r) * K + kb + kk;
                if (k4ok && kb + kk + 3 < K) v = *(const float4*)ap;
                else {
                    if (kb + kk + 0 < K) v.x = ap[0];
                    if (kb + kk + 1 < K) v.y = ap[1];
                    if (kb + kk + 2 < K) v.z = ap[2];
                    if (kb + kk + 3 < K) v.w = ap[3];
                }
            }
            As[kk + 0][r] = v.x; As[kk + 1][r] = v.y;
            As[kk + 2][r] = v.z; As[kk + 3][r] = v.w;
        }
        // B tile: 1 float4 per thread
        {
            int r = tid >> 2;
            int kk = (tid & 3) << 2;
            float4 v = make_float4(0.f, 0.f, 0.f, 0.f);
            if (n0 + r < N) {
                const float* bp = B + (size_t)(n0 + r) * K + kb + kk;
                if (k4ok && kb + kk + 3 < K) v = *(const float4*)bp;
                else {
                    if (kb + kk + 0 < K) v.x = bp[0];
                    if (kb + kk + 1 < K) v.y = bp[1];
                    if (kb + kk + 2 < K) v.z = bp[2];
                    if (kb + kk + 3 < K) v.w = bp[3];
                }
            }
            Bs[kk + 0][r] = v.x; Bs[kk + 1][r] = v.y;
            Bs[kk + 2][r] = v.z; Bs[kk + 3][r] = v.w;
        }
        __syncthreads();
#pragma unroll
        for (int k = 0; k < 16; k++) {
            float4 b4 = *(const float4*)&Bs[k][tx * 4];
            float4 a0 = *(const float4*)&As[k][ty * 8];
            float4 a1 = *(const float4*)&As[k][ty * 8 + 4];
            float a[8] = {a0.x, a0.y, a0.z, a0.w, a1.x, a1.y, a1.z, a1.w};
            float bb[4] = {b4.x, b4.y, b4.z, b4.w};
#pragma unroll
            for (int i = 0; i < 8; i++)
#pragma unroll
                for (int j = 0; j < 4; j++)
                    acc[i][j] += a[i] * bb[j];
        }
        __syncthreads();
    }
#pragma unroll
    for (int i = 0; i < 8; i++) {
        int m = m0 + ty * 8 + i;
        if (m >= M) continue;
#pragma unroll
        for (int j = 0; j < 4; j++) {
            int n = n0 + tx * 4 + j;
            if (n < N) {
                float v = acc[i][j];
                if (bias1) v += bias1[n];
                if (bias2) v += bias2[n];
                C[(size_t)m * N + n] = v;
            }
        }
    }
}

// ---------------- persistent LSTM recurrence ----------------
// 128 CTAs x 640 threads. CTA k owns hidden units [5k, 5k+5).
// warp w: unit u=w>>2, gate g=w&3, row = g*640 + (5k+u). Whh row in registers.
__global__ __launch_bounds__(640, 1) void lstm_rec(
    const float* __restrict__ xW,   // [1024, 2560] (biases folded in)
    const float* __restrict__ Whh,  // [2560, 640]
    float* __restrict__ seq_out)    // [1024, 640]
{
    __shared__ float h_s[640];
    __shared__ float dots[5][4];
    __shared__ float c_s[5];

    const int tid = threadIdx.x;
    const int w = tid >> 5, l = tid & 31;
    const int k = blockIdx.x;
    const int u = w >> 2;
    const int gsel = w & 3;
    const int uglob = 5 * k + u;
    const int row = gsel * 640 + uglob;

    float wreg[20];
    const float* wp = Whh + (size_t)row * 640 + 20 * l;
#pragma unroll
    for (int i = 0; i < 20; i++) wreg[i] = wp[i];
    if (tid < 5) c_s[tid] = 0.f;
    __syncthreads();

    for (int t = 0; t < SEQ; t++) {
        float acc = 0.f;
        if (t > 0) {
            h_s[tid] = __ldcg(seq_out + (size_t)(t - 1) * 640 + tid);
            __syncthreads();
            const float4* hp = (const float4*)(h_s + 20 * l);
#pragma unroll
            for (int i = 0; i < 5; i++) {
                float4 v = hp[i];
                acc += wreg[4 * i + 0] * v.x + wreg[4 * i + 1] * v.y
                     + wreg[4 * i + 2] * v.z + wreg[4 * i + 3] * v.w;
            }
        }
#pragma unroll
        for (int off = 16; off > 0; off >>= 1)
            acc += __shfl_down_sync(0xffffffffu, acc, off);
        if (l == 0) dots[u][gsel] = acc;
        __syncthreads();

        if (tid < 5) {
            const int uu = tid;
            const int ug = 5 * k + uu;
            const float* xwt = xW + (size_t)t * G4;
            float gi = xwt[ug]        + dots[uu][0];
            float gf = xwt[640 + ug]  + dots[uu][1];
            float gg = xwt[1280 + ug] + dots[uu][2];
            float go = xwt[1920 + ug] + dots[uu][3];
            float iv = 1.f / (1.f + __expf(-gi));
            float fv = 1.f / (1.f + __expf(-gf));
            float gv = tanhf(gg);
            float ov = 1.f / (1.f + __expf(-go));
            float c = fv * c_s[uu] + iv * gv;
            c_s[uu] = c;
            seq_out[(size_t)t * 640 + ug] = ov * tanhf(c);
        }
        grid_barrier_dev();
    }
}

// ---------------- graph prep ----------------
__global__ void zero_deg(int* deg) {
    int i = blockIdx.x * blockDim.x + threadIdx.x;
    if (i < NNODES) deg[i] = 0;
}
__global__ void count_deg(const int* __restrict__ dst, int* deg) {
    int e = blockIdx.x * blockDim.x + threadIdx.x;
    if (e < NEDGES) atomicAdd(&deg[dst[e]], 1);
}
__global__ void finalize_deg(const int* __restrict__ deg, float* dinv, float* selfnorm) {
    int i = blockIdx.x * blockDim.x + threadIdx.x;
    if (i < NNODES) {
        float d = rsqrtf((float)(deg[i] + 1));   // +1 self loop
        dinv[i] = d;
        selfnorm[i] = d * d;
    }
}
__global__ void edge_norm(const int* __restrict__ src, const int* __restrict__ dst,
                          const float* __restrict__ dinv, float* enorm) {
    int e = blockIdx.x * blockDim.x + threadIdx.x;
    if (e < NEDGES) enorm[e] = dinv[src[e]] * dinv[dst[e]];
}
__global__ void transpose_k(const float* __restrict__ W, float* __restrict__ Wt,
                            int Cin, int Cout) {
    int idx = blockIdx.x * blockDim.x + threadIdx.x;
    if (idx < Cin * Cout) {
        int i = idx / Cout, o = idx % Cout;
        Wt[o * Cin + i] = W[idx];
    }
}

// ---------------- GCN scatter ----------------
__global__ void scatter_init(const float* __restrict__ h, const float* __restrict__ selfnorm,
                             float* __restrict__ y, int C) {
    int idx = blockIdx.x * blockDim.x + threadIdx.x;
    if (idx < NNODES * C) {
        int i = idx / C;
        y[idx] = selfnorm[i] * h[idx];
    }
}
__global__ void scatter_edges(const float* __restrict__ h, const float* __restrict__ enorm,
                              const int* __restrict__ src, const int* __restrict__ dst,
                              float* __restrict__ y, int C) {
    int idx = blockIdx.x * blockDim.x + threadIdx.x;
    if (idx < NEDGES * C) {
        int e = idx / C, c = idx - e * C;
        atomicAdd(&y[dst[e] * C + c], enorm[e] * h[src[e] * C + c]);
    }
}

// ---------------- bias + leaky + batchnorm (per-column CTA) ----------------
__global__ void bias_leaky_bn(const float* __restrict__ y, const float* __restrict__ b,
                              float* __restrict__ out, int C) {
    const int c = blockIdx.x;
    const int tid = threadIdx.x;
    const float bias = b[c];
    float s = 0.f, sq = 0.f;
    for (int r = tid; r < NNODES; r += 256) {
        float v = y[r * C + c] + bias;
        v = (v > 0.f) ? v : 0.01f * v;
        s += v; sq += v * v;
    }
    __shared__ float rs[256], rq[256];
    rs[tid] = s; rq[tid] = sq;
    __syncthreads();
    for (int o = 128; o > 0; o >>= 1) {
        if (tid < o) { rs[tid] += rs[tid + o]; rq[tid] += rq[tid + o]; }
        __syncthreads();
    }
    float mean = rs[0] * (1.f / NNODES);
    float var = rq[0] * (1.f / NNODES) - mean * mean;
    float rstd = rsqrtf(var + 1e-5f);
    for (int r = tid; r < NNODES; r += 256) {
        float v = y[r * C + c] + bias;
        v = (v > 0.f) ? v : 0.01f * v;
        out[r * C + c] = (v - mean) * rstd;
    }
}

// ---------------- head: segment sum + concat + 3 FC ----------------
__global__ void head_kernel(const float* __restrict__ x,   // [1024, 50]
                            const float* __restrict__ gender, const float* __restrict__ handed,
                            const float* __restrict__ W1, const float* __restrict__ b1,
                            const float* __restrict__ W2, const float* __restrict__ b2,
                            const float* __restrict__ W3, const float* __restrict__ b3,
                            float* __restrict__ out) {
    const int b = blockIdx.x;
    const int tid = threadIdx.x;
    __shared__ float feat[52];
    __shared__ float y1[32], y2[16];
    if (tid < 50) {
        float s = 0.f;
        for (int r = 0; r < 64; r++) s += x[(b * 64 + r) * 50 + tid];
        feat[tid] = s;
    }
    if (tid == 50) feat[50] = gender[b];
    if (tid == 51) feat[51] = handed[b];
    __syncthreads();
    if (tid < 32) {
        float s = b1[tid];
        for (int i = 0; i < 52; i++) s += feat[i] * W1[tid * 52 + i];
        y1[tid] = s;
    }
    __syncthreads();
    if (tid < 16) {
        float s = b2[tid];
        for (int i = 0; i < 32; i++) s += y1[i] * W2[tid * 32 + i];
        y2[tid] = s;
    }
    __syncthreads();
    if (tid == 0) {
        float s = b3[0];
        for (int i = 0; i < 16; i++) s += y2[i] * W3[i];
        out[b] = s;
    }
}

// ---------------- host ----------------
extern "C" void kernel_launch(void* const* d_in, const int* in_sizes, int n_in,
                              void* d_out, int out_size) {
    const float* x_in   = (const float*)d_in[0];
    const int*   eidx   = (const int*)d_in[1];
    const float* gender = (const float*)d_in[2];
    const float* handed = (const float*)d_in[3];
    const float* Wih[3] = {(const float*)d_in[4], (const float*)d_in[8],  (const float*)d_in[12]};
    const float* Whh[3] = {(const float*)d_in[5], (const float*)d_in[9],  (const float*)d_in[13]};
    const float* bih[3] = {(const float*)d_in[6], (const float*)d_in[10], (const float*)d_in[14]};
    const float* bhh[3] = {(const float*)d_in[7], (const float*)d_in[11], (const float*)d_in[15]};
    const float* gcnW[4] = {(const float*)d_in[16], (const float*)d_in[18], (const float*)d_in[20], (const float*)d_in[22]};
    const float* gcnB[4] = {(const float*)d_in[17], (const float*)d_in[19], (const float*)d_in[21], (const float*)d_in[23]};
    const float* fcW[3] = {(const float*)d_in[24], (const float*)d_in[26], (const float*)d_in[28]};
    const float* fcB[3] = {(const float*)d_in[25], (const float*)d_in[27], (const float*)d_in[29]};

    float *xW, *bufA, *bufB, *gh, *gy, *Wt, *dinv, *selfnorm, *enorm;
    int* deg;
    cudaGetSymbolAddress((void**)&xW, g_xW);
    cudaGetSymbolAddress((void**)&bufA, g_bufA);
    cudaGetSymbolAddress((void**)&bufB, g_bufB);
    cudaGetSymbolAddress((void**)&gh, g_gh);
    cudaGetSymbolAddress((void**)&gy, g_gy);
    cudaGetSymbolAddress((void**)&Wt, g_Wt);
    cudaGetSymbolAddress((void**)&deg, g_deg);
    cudaGetSymbolAddress((void**)&dinv, g_dinv);
    cudaGetSymbolAddress((void**)&selfnorm, g_selfnorm);
    cudaGetSymbolAddress((void**)&enorm, g_enorm);

    const int* src = eidx;
    const int* dst = eidx + NEDGES;
    dim3 tb(16, 16);

    // ---- LSTM ----
    sgemm_nt<<<dim3(G4 / 64, SEQ / 128), tb>>>(x_in, Wih[0], bih[0], bhh[0], xW, SEQ, G4, 8500);
    lstm_rec<<<128, 640>>>(xW, Whh[0], bufA);
    sgemm_nt<<<dim3(G4 / 64, SEQ / 128), tb>>>(bufA, Wih[1], bih[1], bhh[1], xW, SEQ, G4, HDIM);
    lstm_rec<<<128, 640>>>(xW, Whh[1], bufB);
    sgemm_nt<<<dim3(G4 / 64, SEQ / 128), tb>>>(bufB, Wih[2], bih[2], bhh[2], xW, SEQ, G4, HDIM);
    lstm_rec<<<128, 640>>>(xW, Whh[2], bufA);

    // ---- graph prep ----
    zero_deg<<<4, 256>>>(deg);
    count_deg<<<NEDGES / 256, 256>>>(dst, deg);
    finalize_deg<<<4, 256>>>(deg, dinv, selfnorm);
    edge_norm<<<NEDGES / 256, 256>>>(src, dst, dinv, enorm);

    // ---- GCN layers ----
    const int cins[4]  = {640, 320, 180, 90};
    const int couts[4] = {320, 180, 90, 50};
    float* xcur = bufA;
    float* xnext = bufB;
    for (int l = 0; l < 4; l++) {
        int Cin = cins[l], Cout = couts[l];
        transpose_k<<<(Cin * Cout + 255) / 256, 256>>>(gcnW[l], Wt, Cin, Cout);
        sgemm_nt<<<dim3((Cout + 63) / 64, NNODES / 128), tb>>>(xcur, Wt, nullptr, nullptr,
                                                               gh, NNODES, Cout, Cin);
        scatter_init<<<(NNODES * Cout + 255) / 256, 256>>>(gh, selfnorm, gy, Cout);
        scatter_edges<<<(NEDGES * Cout + 255) / 256, 256>>>(gh, enorm, src, dst, gy, Cout);
        bias_leaky_bn<<<Cout, 256>>>(gy, gcnB[l], xnext, Cout);
        float* tmp = xcur; xcur = xnext; xnext = tmp;
    }

    // ---- head ----
    head_kernel<<<BSZ, 64>>>(xcur, gender, handed,
                             fcW[0], fcB[0], fcW[1], fcB[1], fcW[2], fcB[2],
                             (float*)d_out);
}

// round 5
// speedup vs baseline: 1.3890x; 1.3846x over previous
#include <cuda_runtime.h>

#define SEQ     1024
#define HDIM    640
#define G4      2560
#define NNODES  1024
#define NEDGES  16384
#define BSZ     16

// ---------------- scratch (device globals; no runtime allocation) ----------------
__device__ float g_xW[SEQ * G4];          // 10.5 MB  LSTM input projections
__device__ float g_bufA[SEQ * HDIM];      // 2.6 MB   ping
__device__ float g_bufB[SEQ * HDIM];      // 2.6 MB   pong
__device__ float g_gh[NNODES * 320];      // GCN gemm out
__device__ float g_gy[NNODES * 320];      // GCN scatter out
__device__ float g_Wt[640 * 320];         // transposed GCN weight
__device__ int   g_deg[NNODES];
__device__ float g_dinv[NNODES];
__device__ float g_selfnorm[NNODES];
__device__ float g_enorm[NEDGES];
__device__ unsigned g_cnt[SEQ];           // per-timestep publish counters

// ---------------- big fp32 NT GEMM: C[M,N] = A[M,K]*B[N,K]^T (+bias1+bias2) ----------------
// BM=128 BN=128 BK=16, 256 threads, 8x8 per thread, double-buffered smem.
// Requires M%128==0, N%128==0 (true for all LSTM projection calls).
__global__ __launch_bounds__(256) void sgemm128(
    const float* __restrict__ A, const float* __restrict__ B,
    const float* __restrict__ bias1, const float* __restrict__ bias2,
    float* __restrict__ C, int M, int N, int K)
{
    __shared__ float As[2][16][128];
    __shared__ float Bs[2][16][128];
    const int tid = threadIdx.x;
    const int m0 = blockIdx.y * 128, n0 = blockIdx.x * 128;
    const int rowg = (tid >> 4) << 3;   // (tid/16)*8
    const int colg = (tid & 15) << 3;   // (tid%16)*8

    float acc[8][8];
#pragma unroll
    for (int i = 0; i < 8; i++)
#pragma unroll
        for (int j = 0; j < 8; j++) acc[i][j] = 0.f;

    const int ntiles = (K + 15) >> 4;

    // tile load: 2048 floats = 512 float4; thread handles float4 ids tid*2, tid*2+1
    // fid -> r = fid>>2 (0..127), kk = (fid&3)*4
    auto ldtile = [&](const float* __restrict__ P, int base_row, int kb, float4* out) {
#pragma unroll
        for (int i = 0; i < 2; i++) {
            int fid = tid * 2 + i;
            int r = fid >> 2, kk = (fid & 3) << 2;
            float4 v = make_float4(0.f, 0.f, 0.f, 0.f);
            const float* p = P + (size_t)(base_row + r) * K + kb + kk;
            if (kb + kk + 3 < K) v = *(const float4*)p;
            else {
                if (kb + kk + 0 < K) v.x = p[0];
                if (kb + kk + 1 < K) v.y = p[1];
                if (kb + kk + 2 < K) v.z = p[2];
            }
            out[i] = v;
        }
    };
    auto sttile = [&](float (*S)[128], const float4* v) {
#pragma unroll
        for (int i = 0; i < 2; i++) {
            int fid = tid * 2 + i;
            int r = fid >> 2, kk = (fid & 3) << 2;
            S[kk + 0][r] = v[i].x; S[kk + 1][r] = v[i].y;
            S[kk + 2][r] = v[i].z; S[kk + 3][r] = v[i].w;
        }
    };

    float4 pa[2], pb[2];
    ldtile(A, m0, 0, pa);
    ldtile(B, n0, 0, pb);
    sttile(As[0], pa);
    sttile(Bs[0], pb);
    __syncthreads();

    for (int kt = 0; kt < ntiles; kt++) {
        const int cur = kt & 1;
        if (kt + 1 < ntiles) {
            ldtile(A, m0, (kt + 1) * 16, pa);
            ldtile(B, n0, (kt + 1) * 16, pb);
        }
        const float (*Ac)[128] = As[cur];
        const float (*Bc)[128] = Bs[cur];
#pragma unroll
        for (int k = 0; k < 16; k++) {
            float4 a0 = *(const float4*)&Ac[k][rowg];
            float4 a1 = *(const float4*)&Ac[k][rowg + 4];
            float4 b0 = *(const float4*)&Bc[k][colg];
            float4 b1 = *(const float4*)&Bc[k][colg + 4];
            float a[8]  = {a0.x, a0.y, a0.z, a0.w, a1.x, a1.y, a1.z, a1.w};
            float bb[8] = {b0.x, b0.y, b0.z, b0.w, b1.x, b1.y, b1.z, b1.w};
#pragma unroll
            for (int i = 0; i < 8; i++)
#pragma unroll
                for (int j = 0; j < 8; j++)
                    acc[i][j] += a[i] * bb[j];
        }
        if (kt + 1 < ntiles) {
            sttile(As[1 - cur], pa);
            sttile(Bs[1 - cur], pb);
        }
        __syncthreads();
    }

#pragma unroll
    for (int i = 0; i < 8; i++) {
        const int m = m0 + rowg + i;
        float* cp = C + (size_t)m * N + n0 + colg;
#pragma unroll
        for (int j = 0; j < 8; j++) {
            const int n = n0 + colg + j;
            float v = acc[i][j];
            if (bias1) v += bias1[n];
            if (bias2) v += bias2[n];
            cp[j] = v;
        }
    }
}

// ---------------- generic fp32 NT GEMM (GCN path, small N) ----------------
__global__ __launch_bounds__(256) void sgemm_nt(
    const float* __restrict__ A, const float* __restrict__ B,
    const float* __restrict__ bias1, const float* __restrict__ bias2,
    float* __restrict__ C, int M, int N, int K)
{
    __shared__ float As[16][128];
    __shared__ float Bs[16][64];
    const int tx = threadIdx.x, ty = threadIdx.y;
    const int tid = ty * 16 + tx;
    const int m0 = blockIdx.y * 128, n0 = blockIdx.x * 64;

    float acc[8][4];
#pragma unroll
    for (int i = 0; i < 8; i++)
#pragma unroll
        for (int j = 0; j < 4; j++) acc[i][j] = 0.f;

    const bool k4ok = ((K & 3) == 0);
    const int ntiles = (K + 15) >> 4;

    for (int kt = 0; kt < ntiles; kt++) {
        const int kb = kt * 16;
#pragma unroll
        for (int i = 0; i < 2; i++) {
            int fid = tid * 2 + i;
            int r = fid >> 2;
            int kk = (fid & 3) << 2;
            float4 v = make_float4(0.f, 0.f, 0.f, 0.f);
            if (m0 + r < M) {
                const float* ap = A + (size_t)(m0 + r) * K + kb + kk;
                if (k4ok && kb + kk + 3 < K) v = *(const float4*)ap;
                else {
                    if (kb + kk + 0 < K) v.x = ap[0];
                    if (kb + kk + 1 < K) v.y = ap[1];
                    if (kb + kk + 2 < K) v.z = ap[2];
                    if (kb + kk + 3 < K) v.w = ap[3];
                }
            }
            As[kk + 0][r] = v.x; As[kk + 1][r] = v.y;
            As[kk + 2][r] = v.z; As[kk + 3][r] = v.w;
        }
        {
            int r = tid >> 2;
            int kk = (tid & 3) << 2;
            float4 v = make_float4(0.f, 0.f, 0.f, 0.f);
            if (n0 + r < N) {
                const float* bp = B + (size_t)(n0 + r) * K + kb + kk;
                if (k4ok && kb + kk + 3 < K) v = *(const float4*)bp;
                else {
                    if (kb + kk + 0 < K) v.x = bp[0];
                    if (kb + kk + 1 < K) v.y = bp[1];
                    if (kb + kk + 2 < K) v.z = bp[2];
                    if (kb + kk + 3 < K) v.w = bp[3];
                }
            }
            Bs[kk + 0][r] = v.x; Bs[kk + 1][r] = v.y;
            Bs[kk + 2][r] = v.z; Bs[kk + 3][r] = v.w;
        }
        __syncthreads();
#pragma unroll
        for (int k = 0; k < 16; k++) {
            float4 b4 = *(const float4*)&Bs[k][tx * 4];
            float4 a0 = *(const float4*)&As[k][ty * 8];
            float4 a1 = *(const float4*)&As[k][ty * 8 + 4];
            float a[8] = {a0.x, a0.y, a0.z, a0.w, a1.x, a1.y, a1.z, a1.w};
            float bb[4] = {b4.x, b4.y, b4.z, b4.w};
#pragma unroll
            for (int i = 0; i < 8; i++)
#pragma unroll
                for (int j = 0; j < 4; j++)
                    acc[i][j] += a[i] * bb[j];
        }
        __syncthreads();
    }
#pragma unroll
    for (int i = 0; i < 8; i++) {
        int m = m0 + ty * 8 + i;
        if (m >= M) continue;
#pragma unroll
        for (int j = 0; j < 4; j++) {
            int n = n0 + tx * 4 + j;
            if (n < N) {
                float v = acc[i][j];
                if (bias1) v += bias1[n];
                if (bias2) v += bias2[n];
                C[(size_t)m * N + n] = v;
            }
        }
    }
}

// ---------------- counter reset ----------------
__global__ void zero_cnt() {
    int i = blockIdx.x * blockDim.x + threadIdx.x;
    if (i < SEQ) g_cnt[i] = 0u;
}

// ---------------- persistent LSTM recurrence (per-timestep release/acquire counters) ----------------
// 128 CTAs x 640 threads. CTA k owns hidden units [5k, 5k+5).
// warp w: unit u=w>>2, gate g=w&3, row = g*640 + (5k+u). Whh row in registers.
// Publish protocol: after writing h(t), one thread per CTA does red.release.gpu.add(cnt[t], 1).
// Consumers at step t+1 spin on ld.acquire.gpu(cnt[t]) until it reaches 128.
// No write-after-read hazard exists (seq_out rows are distinct per t), so no full barrier needed.
__global__ __launch_bounds__(640, 1) void lstm_rec(
    const float* __restrict__ xW,   // [1024, 2560] (biases folded in)
    const float* __restrict__ Whh,  // [2560, 640]
    float* __restrict__ seq_out)    // [1024, 640]
{
    __shared__ float h_s[640];
    __shared__ float dots[5][4];
    __shared__ float c_s[5];

    const int tid = threadIdx.x;
    const int w = tid >> 5, l = tid & 31;
    const int k = blockIdx.x;
    const int u = w >> 2;
    const int gsel = w & 3;
    const int uglob = 5 * k + u;
    const int row = gsel * 640 + uglob;

    float wreg[20];
    const float* wp = Whh + (size_t)row * 640 + 20 * l;
#pragma unroll
    for (int i = 0; i < 20; i++) wreg[i] = wp[i];
    if (tid < 5) c_s[tid] = 0.f;
    unsigned* cnt = g_cnt;
    __syncthreads();

    for (int t = 0; t < SEQ; t++) {
        // gate threads prefetch xW operands before the wait (off critical path)
        float xg0 = 0.f, xg1 = 0.f, xg2 = 0.f, xg3 = 0.f;
        if (tid < 5) {
            const float* xwt = xW + (size_t)t * G4 + 5 * k + tid;
            xg0 = __ldg(xwt);
            xg1 = __ldg(xwt + 640);
            xg2 = __ldg(xwt + 1280);
            xg3 = __ldg(xwt + 1920);
        }

        float acc = 0.f;
        if (t > 0) {
            if (tid == 0) {
                unsigned v;
                do {
                    asm volatile("ld.acquire.gpu.global.u32 %0, [%1];"
                                 : "=r"(v) : "l"(cnt + (t - 1)) : "memory");
                } while (v < 128u);
            }
            __syncthreads();
            h_s[tid] = __ldcg(seq_out + (size_t)(t - 1) * 640 + tid);
            __syncthreads();
            const float4* hp = (const float4*)(h_s + 20 * l);
#pragma unroll
            for (int i = 0; i < 5; i++) {
                float4 v = hp[i];
                acc += wreg[4 * i + 0] * v.x + wreg[4 * i + 1] * v.y
                     + wreg[4 * i + 2] * v.z + wreg[4 * i + 3] * v.w;
            }
        }
#pragma unroll
        for (int off = 16; off > 0; off >>= 1)
            acc += __shfl_down_sync(0xffffffffu, acc, off);
        if (l == 0) dots[u][gsel] = acc;
        __syncthreads();

        if (tid < 5) {
            const int uu = tid;
            const int ug = 5 * k + uu;
            float gi = xg0 + dots[uu][0];
            float gf = xg1 + dots[uu][1];
            float gg = xg2 + dots[uu][2];
            float go = xg3 + dots[uu][3];
            float iv = 1.f / (1.f + __expf(-gi));
            float fv = 1.f / (1.f + __expf(-gf));
            float gv = tanhf(gg);
            float ov = 1.f / (1.f + __expf(-go));
            float c = fv * c_s[uu] + iv * gv;
            c_s[uu] = c;
            seq_out[(size_t)t * 640 + ug] = ov * tanhf(c);
        }
        __syncthreads();   // order gate-thread stores before the release
        if (tid == 0) {
            asm volatile("red.release.gpu.global.add.u32 [%0], %1;"
                         :: "l"(cnt + t), "r"(1u) : "memory");
        }
    }
}

// ---------------- graph prep ----------------
__global__ void zero_deg(int* deg) {
    int i = blockIdx.x * blockDim.x + threadIdx.x;
    if (i < NNODES) deg[i] = 0;
}
__global__ void count_deg(const int* __restrict__ dst, int* deg) {
    int e = blockIdx.x * blockDim.x + threadIdx.x;
    if (e < NEDGES) atomicAdd(&deg[dst[e]], 1);
}
__global__ void finalize_deg(const int* __restrict__ deg, float* dinv, float* selfnorm) {
    int i = blockIdx.x * blockDim.x + threadIdx.x;
    if (i < NNODES) {
        float d = rsqrtf((float)(deg[i] + 1));   // +1 self loop
        dinv[i] = d;
        selfnorm[i] = d * d;
    }
}
__global__ void edge_norm(const int* __restrict__ src, const int* __restrict__ dst,
                          const float* __restrict__ dinv, float* enorm) {
    int e = blockIdx.x * blockDim.x + threadIdx.x;
    if (e < NEDGES) enorm[e] = dinv[src[e]] * dinv[dst[e]];
}
__global__ void transpose_k(const float* __restrict__ W, float* __restrict__ Wt,
                            int Cin, int Cout) {
    int idx = blockIdx.x * blockDim.x + threadIdx.x;
    if (idx < Cin * Cout) {
        int i = idx / Cout, o = idx % Cout;
        Wt[o * Cin + i] = W[idx];
    }
}

// ---------------- GCN scatter ----------------
__global__ void scatter_init(const float* __restrict__ h, const float* __restrict__ selfnorm,
                             float* __restrict__ y, int C) {
    int idx = blockIdx.x * blockDim.x + threadIdx.x;
    if (idx < NNODES * C) {
        int i = idx / C;
        y[idx] = selfnorm[i] * h[idx];
    }
}
__global__ void scatter_edges(const float* __restrict__ h, const float* __restrict__ enorm,
                              const int* __restrict__ src, const int* __restrict__ dst,
                              float* __restrict__ y, int C) {
    int idx = blockIdx.x * blockDim.x + threadIdx.x;
    if (idx < NEDGES * C) {
        int e = idx / C, c = idx - e * C;
        atomicAdd(&y[dst[e] * C + c], enorm[e] * h[src[e] * C + c]);
    }
}

// ---------------- bias + leaky + batchnorm (per-column CTA) ----------------
__global__ void bias_leaky_bn(const float* __restrict__ y, const float* __restrict__ b,
                              float* __restrict__ out, int C) {
    const int c = blockIdx.x;
    const int tid = threadIdx.x;
    const float bias = b[c];
    float s = 0.f, sq = 0.f;
    for (int r = tid; r < NNODES; r += 256) {
        float v = y[r * C + c] + bias;
        v = (v > 0.f) ? v : 0.01f * v;
        s += v; sq += v * v;
    }
    __shared__ float rs[256], rq[256];
    rs[tid] = s; rq[tid] = sq;
    __syncthreads();
    for (int o = 128; o > 0; o >>= 1) {
        if (tid < o) { rs[tid] += rs[tid + o]; rq[tid] += rq[tid + o]; }
        __syncthreads();
    }
    float mean = rs[0] * (1.f / NNODES);
    float var = rq[0] * (1.f / NNODES) - mean * mean;
    float rstd = rsqrtf(var + 1e-5f);
    for (int r = tid; r < NNODES; r += 256) {
        float v = y[r * C + c] + bias;
        v = (v > 0.f) ? v : 0.01f * v;
        out[r * C + c] = (v - mean) * rstd;
    }
}

// ---------------- head: segment sum + concat + 3 FC ----------------
__global__ void head_kernel(const float* __restrict__ x,   // [1024, 50]
                            const float* __restrict__ gender, const float* __restrict__ handed,
                            const float* __restrict__ W1, const float* __restrict__ b1,
                            const float* __restrict__ W2, const float* __restrict__ b2,
                            const float* __restrict__ W3, const float* __restrict__ b3,
                            float* __restrict__ out) {
    const int b = blockIdx.x;
    const int tid = threadIdx.x;
    __shared__ float feat[52];
    __shared__ float y1[32], y2[16];
    if (tid < 50) {
        float s = 0.f;
        for (int r = 0; r < 64; r++) s += x[(b * 64 + r) * 50 + tid];
        feat[tid] = s;
    }
    if (tid == 50) feat[50] = gender[b];
    if (tid == 51) feat[51] = handed[b];
    __syncthreads();
    if (tid < 32) {
        float s = b1[tid];
        for (int i = 0; i < 52; i++) s += feat[i] * W1[tid * 52 + i];
        y1[tid] = s;
    }
    __syncthreads();
    if (tid < 16) {
        float s = b2[tid];
        for (int i = 0; i < 32; i++) s += y1[i] * W2[tid * 32 + i];
        y2[tid] = s;
    }
    __syncthreads();
    if (tid == 0) {
        float s = b3[0];
        for (int i = 0; i < 16; i++) s += y2[i] * W3[i];
        out[b] = s;
    }
}

// ---------------- host ----------------
extern "C" void kernel_launch(void* const* d_in, const int* in_sizes, int n_in,
                              void* d_out, int out_size) {
    const float* x_in   = (const float*)d_in[0];
    const int*   eidx   = (const int*)d_in[1];
    const float* gender = (const float*)d_in[2];
    const float* handed = (const float*)d_in[3];
    const float* Wih[3] = {(const float*)d_in[4], (const float*)d_in[8],  (const float*)d_in[12]};
    const float* Whh[3] = {(const float*)d_in[5], (const float*)d_in[9],  (const float*)d_in[13]};
    const float* bih[3] = {(const float*)d_in[6], (const float*)d_in[10], (const float*)d_in[14]};
    const float* bhh[3] = {(const float*)d_in[7], (const float*)d_in[11], (const float*)d_in[15]};
    const float* gcnW[4] = {(const float*)d_in[16], (const float*)d_in[18], (const float*)d_in[20], (const float*)d_in[22]};
    const float* gcnB[4] = {(const float*)d_in[17], (const float*)d_in[19], (const float*)d_in[21], (const float*)d_in[23]};
    const float* fcW[3] = {(const float*)d_in[24], (const float*)d_in[26], (const float*)d_in[28]};
    const float* fcB[3] = {(const float*)d_in[25], (const float*)d_in[27], (const float*)d_in[29]};

    float *xW, *bufA, *bufB, *gh, *gy, *Wt, *dinv, *selfnorm, *enorm;
    int* deg;
    cudaGetSymbolAddress((void**)&xW, g_xW);
    cudaGetSymbolAddress((void**)&bufA, g_bufA);
    cudaGetSymbolAddress((void**)&bufB, g_bufB);
    cudaGetSymbolAddress((void**)&gh, g_gh);
    cudaGetSymbolAddress((void**)&gy, g_gy);
    cudaGetSymbolAddress((void**)&Wt, g_Wt);
    cudaGetSymbolAddress((void**)&deg, g_deg);
    cudaGetSymbolAddress((void**)&dinv, g_dinv);
    cudaGetSymbolAddress((void**)&selfnorm, g_selfnorm);
    cudaGetSymbolAddress((void**)&enorm, g_enorm);

    const int* src = eidx;
    const int* dst = eidx + NEDGES;
    dim3 tb(16, 16);

    // ---- LSTM ----
    sgemm128<<<dim3(G4 / 128, SEQ / 128), 256>>>(x_in, Wih[0], bih[0], bhh[0], xW, SEQ, G4, 8500);
    zero_cnt<<<4, 256>>>();
    lstm_rec<<<128, 640>>>(xW, Whh[0], bufA);
    sgemm128<<<dim3(G4 / 128, SEQ / 128), 256>>>(bufA, Wih[1], bih[1], bhh[1], xW, SEQ, G4, HDIM);
    zero_cnt<<<4, 256>>>();
    lstm_rec<<<128, 640>>>(xW, Whh[1], bufB);
    sgemm128<<<dim3(G4 / 128, SEQ / 128), 256>>>(bufB, Wih[2], bih[2], bhh[2], xW, SEQ, G4, HDIM);
    zero_cnt<<<4, 256>>>();
    lstm_rec<<<128, 640>>>(xW, Whh[2], bufA);

    // ---- graph prep ----
    zero_deg<<<4, 256>>>(deg);
    count_deg<<<NEDGES / 256, 256>>>(dst, deg);
    finalize_deg<<<4, 256>>>(deg, dinv, selfnorm);
    edge_norm<<<NEDGES / 256, 256>>>(src, dst, dinv, enorm);

    // ---- GCN layers ----
    const int cins[4]  = {640, 320, 180, 90};
    const int couts[4] = {320, 180, 90, 50};
    float* xcur = bufA;
    float* xnext = bufB;
    for (int l = 0; l < 4; l++) {
        int Cin = cins[l], Cout = couts[l];
        transpose_k<<<(Cin * Cout + 255) / 256, 256>>>(gcnW[l], Wt, Cin, Cout);
        sgemm_nt<<<dim3((Cout + 63) / 64, NNODES / 128), tb>>>(xcur, Wt, nullptr, nullptr,
                                                               gh, NNODES, Cout, Cin);
        scatter_init<<<(NNODES * Cout + 255) / 256, 256>>>(gh, selfnorm, gy, Cout);
        scatter_edges<<<(NEDGES * Cout + 255) / 256, 256>>>(gh, enorm, src, dst, gy, Cout);
        bias_leaky_bn<<<Cout, 256>>>(gy, gcnB[l], xnext, Cout);
        float* tmp = xcur; xcur = xnext; xnext = tmp;
    }

    // ---- head ----
    head_kernel<<<BSZ, 64>>>(xcur, gender, handed,
                             fcW[0], fcB[0], fcW[1], fcB[1], fcW[2], fcB[2],
                             (float*)d_out);
}